// round 5
// baseline (speedup 1.0000x reference)
#include <cuda_runtime.h>
#include <cstddef>
#include <cstdint>

#define BB 4
#define NN 4096
#define KK 16
#define DP 64
#define DM 256
#define NPTS (BB*NN)
#define MTOT (NPTS*KK)

// ---------------- device-global scratch (no allocs allowed) ----------------
__device__ float g_WpreT[DP*DM];
__device__ float g_WQT  [DM*DM];
__device__ float g_WKT  [DM*DM];
__device__ float g_WVT  [DM*DM];
__device__ float g_WprojT[DM*DM];
__device__ float g_WpostT[DM*DP];
__device__ float g_Wp2r [DM*DM];   // tf32-rounded, row-major [n][k]
__device__ float g_Wa1r [DM*DM];
__device__ float g_Wa2r [DM*DM];
__device__ float g_Q [NPTS*DM];
__device__ float g_Kf[NPTS*DM];
__device__ float g_Vf[NPTS*DM];
__device__ int   g_idx[NPTS*KK];
__device__ float g_res[(size_t)NPTS*DM];

// ---------------- helpers ----------------
__device__ __forceinline__ uint32_t smem_u32(const void* p) {
    uint32_t a;
    asm("{ .reg .u64 t; cvta.to.shared.u64 t, %1; cvt.u32.u64 %0, t; }" : "=r"(a) : "l"(p));
    return a;
}
__device__ __forceinline__ float rna_tf32(float x) {
    uint32_t r;
    asm("cvt.rna.tf32.f32 %0, %1;" : "=r"(r) : "f"(x));
    return __uint_as_float(r);
}
#define CP16(dst, src) asm volatile("cp.async.cg.shared.global [%0], [%1], 16;" :: "r"(dst), "l"(src) : "memory")
#define CP_COMMIT()    asm volatile("cp.async.commit_group;" ::: "memory")
#define CP_WAIT1()     asm volatile("cp.async.wait_group 1;" ::: "memory")
#define CP_WAIT0()     asm volatile("cp.async.wait_group 0;" ::: "memory")
#define LDSM4(r0,r1,r2,r3,a) \
    asm volatile("ldmatrix.sync.aligned.m8n8.x4.shared.b16 {%0,%1,%2,%3}, [%4];" \
                 : "=r"(r0),"=r"(r1),"=r"(r2),"=r"(r3) : "r"(a))

__device__ __forceinline__ void mma1688(float* c, const uint32_t* a, uint32_t b0, uint32_t b1) {
    asm volatile("mma.sync.aligned.m16n8k8.row.col.f32.tf32.tf32.f32 "
        "{%0,%1,%2,%3}, {%4,%5,%6,%7}, {%8,%9}, {%0,%1,%2,%3};"
        : "+f"(c[0]), "+f"(c[1]), "+f"(c[2]), "+f"(c[3])
        : "r"(a[0]), "r"(a[1]), "r"(a[2]), "r"(a[3]), "r"(b0), "r"(b1));
}

// ---------------- weight prep ----------------
__global__ void prep_kernel(const float* __restrict__ W_pre,
                            const float* __restrict__ WQ,  const float* __restrict__ WK,
                            const float* __restrict__ WV,  const float* __restrict__ Wproj,
                            const float* __restrict__ W_post,
                            const float* __restrict__ Wp2, const float* __restrict__ Wa1,
                            const float* __restrict__ Wa2)
{
    int t = blockIdx.x * blockDim.x + threadIdx.x;
    if (t < DM*DP) {
        int fo = t >> 6, j = t & 63;
        g_WpreT[j*DM + fo] = W_pre[t];
    }
    if (t < DP*DM) {
        int p = t >> 8, j = t & 255;
        g_WpostT[j*DP + p] = W_post[t];
    }
    if (t < DM*DM) {
        int r = t >> 8, c = t & 255;
        g_WQT   [c*DM + r] = WQ[t];
        g_WKT   [c*DM + r] = WK[t];
        g_WVT   [c*DM + r] = WV[t];
        g_WprojT[c*DM + r] = Wproj[t];
        g_Wp2r[t] = rna_tf32(Wp2[t]);
        g_Wa1r[t] = rna_tf32(Wa1[t]);
        g_Wa2r[t] = rna_tf32(Wa2[t]);
    }
}

// ---------------- kNN ----------------
__global__ void __launch_bounds__(256) knn_kernel(const float* __restrict__ xyz)
{
    extern __shared__ float4 pts[];
    int b     = blockIdx.x >> 4;
    int chunk = blockIdx.x & 15;
    const float* xb = xyz + (size_t)b * NN * 3;
    for (int m = threadIdx.x; m < NN; m += 256)
        pts[m] = make_float4(xb[m*3], xb[m*3+1], xb[m*3+2], 0.f);
    __syncthreads();

    int qi = chunk * 256 + threadIdx.x;
    float4 qp = pts[qi];

    float bd[KK]; int bi[KK];
    #pragma unroll
    for (int i = 0; i < KK; i++) { bd[i] = 3.4e38f; bi[i] = i; }
    float worst = 3.4e38f; int wpos = 0;

    for (int m = 0; m < NN; m++) {
        float4 p = pts[m];
        float dx = qp.x - p.x, dy = qp.y - p.y, dz = qp.z - p.z;
        float d = fmaf(dx, dx, fmaf(dy, dy, dz * dz));
        if (d < worst) {
            bd[wpos] = d; bi[wpos] = m;
            worst = bd[0]; wpos = 0;
            #pragma unroll
            for (int i = 1; i < KK; i++)
                if (bd[i] > worst) { worst = bd[i]; wpos = i; }
        }
    }
    #pragma unroll
    for (int i = 0; i < KK; i++)
        g_idx[(size_t)(b*NN + qi)*KK + i] = bi[i];
}

// ---------------- SIMT gemv helpers (qkv + final) ----------------
template<int LEN>
__device__ __forceinline__ void gemv16(const float* __restrict__ WT,
                                       const float* __restrict__ hb,
                                       int f, float* acc)
{
    #pragma unroll 4
    for (int j = 0; j < LEN; j++) {
        float w = __ldg(&WT[j*DM + f]);
        const float4* hr = reinterpret_cast<const float4*>(hb + j*20);
        float4 h0 = hr[0], h1 = hr[1], h2 = hr[2], h3 = hr[3];
        acc[0]  = fmaf(w, h0.x, acc[0]);  acc[1]  = fmaf(w, h0.y, acc[1]);
        acc[2]  = fmaf(w, h0.z, acc[2]);  acc[3]  = fmaf(w, h0.w, acc[3]);
        acc[4]  = fmaf(w, h1.x, acc[4]);  acc[5]  = fmaf(w, h1.y, acc[5]);
        acc[6]  = fmaf(w, h1.z, acc[6]);  acc[7]  = fmaf(w, h1.w, acc[7]);
        acc[8]  = fmaf(w, h2.x, acc[8]);  acc[9]  = fmaf(w, h2.y, acc[9]);
        acc[10] = fmaf(w, h2.z, acc[10]); acc[11] = fmaf(w, h2.w, acc[11]);
        acc[12] = fmaf(w, h3.x, acc[12]); acc[13] = fmaf(w, h3.y, acc[13]);
        acc[14] = fmaf(w, h3.z, acc[14]); acc[15] = fmaf(w, h3.w, acc[15]);
    }
}

__device__ __forceinline__ void warp_bfly2(float& s, float& s2)
{
    #pragma unroll
    for (int o = 16; o; o >>= 1) {
        s  += __shfl_xor_sync(0xffffffffu, s , o);
        s2 += __shfl_xor_sync(0xffffffffu, s2, o);
    }
}

__device__ __forceinline__ void qkv_proj(const float* __restrict__ WT,
    const float* __restrict__ ibuf, float* obuf,
    const float* __restrict__ gg, const float* __restrict__ bb,
    float* __restrict__ outg, int f)
{
    float acc[16];
    #pragma unroll
    for (int k = 0; k < 16; k++) acc[k] = 0.f;
    gemv16<DM>(WT, ibuf, f, acc);
    #pragma unroll
    for (int k = 0; k < 16; k++) obuf[k*260 + f] = acc[k];
    __syncthreads();

    int wid = f >> 5, lane = f & 31;
    #pragma unroll
    for (int pp = 0; pp < 2; pp++) {
        int p = wid*2 + pp;
        const float* row = &obuf[p*260];
        float v[8]; float s = 0.f, s2 = 0.f;
        #pragma unroll
        for (int i = 0; i < 8; i++) { float x = row[lane*8 + i]; v[i] = x; s += x; s2 += x*x; }
        warp_bfly2(s, s2);
        float mu  = s  * (1.f/DM);
        float var = s2 * (1.f/DM) - mu*mu;
        float rs  = rsqrtf(var + 1e-5f);
        #pragma unroll
        for (int i = 0; i < 8; i++) {
            int c = lane*8 + i;
            outg[(size_t)p*DM + c] = (v[i] - mu) * rs * gg[c] + bb[c];
        }
    }
    __syncthreads();
}

__global__ void __launch_bounds__(256) qkv_kernel(
    const float* __restrict__ features, const float* __restrict__ b_pre,
    const float* __restrict__ gdm, const float* __restrict__ bdm)
{
    int p0 = blockIdx.x * 16;
    int f  = threadIdx.x;
    __shared__ __align__(16) float featsm[DP*20];
    __shared__ __align__(16) float ibuf  [DM*20];
    __shared__ float obuf[16*260];

    for (int t = f; t < 16*DP; t += 256) {
        int p = t >> 6, j = t & 63;
        featsm[j*20 + p] = features[(size_t)(p0 + p)*DP + j];
    }
    __syncthreads();

    float acc[16];
    float bp = b_pre[f];
    #pragma unroll
    for (int k = 0; k < 16; k++) acc[k] = bp;
    gemv16<DP>(g_WpreT, featsm, f, acc);
    #pragma unroll
    for (int k = 0; k < 16; k++) ibuf[f*20 + k] = acc[k];
    __syncthreads();

    qkv_proj(g_WQT, ibuf, obuf, gdm, bdm, g_Q  + (size_t)p0*DM, f);
    qkv_proj(g_WKT, ibuf, obuf, gdm, bdm, g_Kf + (size_t)p0*DM, f);
    qkv_proj(g_WVT, ibuf, obuf, gdm, bdm, g_Vf + (size_t)p0*DM, f);
}

// ---------------- fused mega-kernel: h1 -> GEMM1 -> t/U -> GEMM2 -> GEMM3 -> softmax
// Per CTA: 64 rows (4 points), 256 cols. 8 warps, warp w owns cols [w*32, w*32+32),
// all 64 rows (4 m16 tiles x 4 n8 tiles -> acc[4][4][4]).
// A buffer in smem: 64 rows x pitch 260 floats (1040 B; 1040 % 128 == 16 -> LDSM clean).
// B chunks: 256 rows x 36 floats (144 B pitch), double buffered.
#define APITCH  260
#define ABYTES  (64*APITCH*4)            // 66560
#define BBYTES  (256*144)                // 36864
#define MEGA_SMEM (ABYTES + 2*BBYTES)    // 140288

struct MegaSm {
    // raw layout handled by byte offsets
};

__device__ __forceinline__ void load_bchunk(uint32_t sB, const float* __restrict__ Bw,
                                            int kt, int buf, int tid)
{
    uint32_t base = sB + (uint32_t)buf*BBYTES;
    #pragma unroll
    for (int i = 0; i < 8; i++) {
        int ch = tid + i*256;
        int r = ch >> 3, c = ch & 7;
        CP16(base + r*144 + c*16, Bw + (size_t)r*256 + kt*32 + c*4);
    }
}

__device__ __forceinline__ void run_stage(const float* __restrict__ Bw,
                                          float acc[4][4][4],
                                          uint32_t sA, uint32_t sB,
                                          int tid, int lane, int w)
{
    #pragma unroll
    for (int mt = 0; mt < 4; mt++)
        #pragma unroll
        for (int nt = 0; nt < 4; nt++)
            #pragma unroll
            for (int j = 0; j < 4; j++) acc[mt][nt][j] = 0.f;

    const uint32_t aBase = sA + ((lane & 7) + ((lane >> 3) & 1)*8)*1040
                              + ((lane >> 4) & 1)*16;
    const uint32_t bBase = sB + ((uint32_t)w*32 + (lane & 7) + ((lane >> 4) & 1)*8)*144
                              + ((lane >> 3) & 1)*16;

    load_bchunk(sB, Bw, 0, 0, tid); CP_COMMIT();
    load_bchunk(sB, Bw, 1, 1, tid); CP_COMMIT();

    for (int kt = 0; kt < 8; kt++) {
        int buf = kt & 1;
        if (kt < 6) { CP_WAIT1(); } else { CP_WAIT0(); }
        __syncthreads();

        uint32_t ab = aBase + kt*128;
        uint32_t bb = bBase + (uint32_t)buf*BBYTES;
        #pragma unroll
        for (int ks = 0; ks < 4; ks++) {
            uint32_t af[4][4], bf[2][4];
            #pragma unroll
            for (int mt = 0; mt < 4; mt++)
                LDSM4(af[mt][0], af[mt][1], af[mt][2], af[mt][3],
                      ab + mt*16640 + ks*32);
            #pragma unroll
            for (int ntp = 0; ntp < 2; ntp++)
                LDSM4(bf[ntp][0], bf[ntp][1], bf[ntp][2], bf[ntp][3],
                      bb + ntp*2304 + ks*32);
            #pragma unroll
            for (int mt = 0; mt < 4; mt++)
                #pragma unroll
                for (int nt = 0; nt < 4; nt++)
                    mma1688(acc[mt][nt], af[mt],
                            bf[nt >> 1][(nt & 1)*2], bf[nt >> 1][(nt & 1)*2 + 1]);
        }
        __syncthreads();
        if (kt + 2 < 8) { load_bchunk(sB, Bw, kt + 2, buf, tid); CP_COMMIT(); }
    }
}

__global__ void __launch_bounds__(256) mega_kernel(
    const float* __restrict__ xyz, const float* __restrict__ Wp1,
    const float* __restrict__ Wp2r, const float* __restrict__ Wa1r,
    const float* __restrict__ Wa2r)
{
    extern __shared__ float smemf[];
    uint32_t sA = smem_u32(smemf);
    uint32_t sB = sA + ABYTES;

    const int tid  = threadIdx.x;
    const int lane = tid & 31, w = tid >> 5;
    const int m0    = blockIdx.x * 64;
    const int pbase = m0 >> 4;             // 4 points per CTA
    const int bq    = pbase >> 12;

    __shared__ float rel3[64][3];
    __shared__ int   idxs[64];

    // ---- prologue: rel + neighbor ids ----
    if (tid < 64) {
        int m  = m0 + tid;
        int pt = m >> 4;
        int n  = pt & (NN - 1);
        int id = g_idx[(size_t)pt*KK + (m & 15)];
        idxs[tid] = id;
        const float* xb = xyz + (size_t)bq*NN*3;
        rel3[tid][0] = xb[n*3 + 0] - xb[id*3 + 0];
        rel3[tid][1] = xb[n*3 + 1] - xb[id*3 + 1];
        rel3[tid][2] = xb[n*3 + 2] - xb[id*3 + 2];
    }
    float w0 = Wp1[tid*3 + 0], w1 = Wp1[tid*3 + 1], w2 = Wp1[tid*3 + 2];
    __syncthreads();

    // ---- h1 = rna(relu(rel @ Wp1^T)) into A buffer; thread owns col f=tid ----
    #pragma unroll 8
    for (int j = 0; j < 64; j++) {
        float h = fmaf(w0, rel3[j][0], fmaf(w1, rel3[j][1], w2*rel3[j][2]));
        smemf[j*APITCH + tid] = rna_tf32(fmaxf(h, 0.f));
    }
    // (visibility to LDSM is guaranteed by the __syncthreads inside run_stage)

    float acc[4][4][4];
    float U[4][4][4];

    // ---- stage 1: pos = h1 @ Wp2^T ----
    run_stage(Wp2r, acc, sA, sB, tid, lane, w);
    __syncthreads();                        // everyone done reading h1

    // epilogue 1: t = rna(q - k + pos) -> A buffer; U = v + pos -> regs
    {
        const int r0b = lane >> 2;          // 0..7
        const int colb = w*32 + (lane & 3)*2;
        #pragma unroll
        for (int mt = 0; mt < 4; mt++) {
            int pt = pbase + mt;
            int r0 = mt*16 + r0b, r1 = r0 + 8;
            const float* qp  = g_Q  + (size_t)pt*DM;
            const float* k0p = g_Kf + ((size_t)(bq << 12) + idxs[r0])*DM;
            const float* k1p = g_Kf + ((size_t)(bq << 12) + idxs[r1])*DM;
            const float* v0p = g_Vf + ((size_t)(bq << 12) + idxs[r0])*DM;
            const float* v1p = g_Vf + ((size_t)(bq << 12) + idxs[r1])*DM;
            #pragma unroll
            for (int nt = 0; nt < 4; nt++) {
                int col = colb + nt*8;
                float2 q  = *(const float2*)(qp  + col);
                float2 ka = *(const float2*)(k0p + col);
                float2 kb = *(const float2*)(k1p + col);
                float2 va = *(const float2*)(v0p + col);
                float2 vb = *(const float2*)(v1p + col);
                float p00 = acc[mt][nt][0], p01 = acc[mt][nt][1];
                float p10 = acc[mt][nt][2], p11 = acc[mt][nt][3];
                *(float2*)(smemf + r0*APITCH + col) =
                    make_float2(rna_tf32(q.x - ka.x + p00), rna_tf32(q.y - ka.y + p01));
                *(float2*)(smemf + r1*APITCH + col) =
                    make_float2(rna_tf32(q.x - kb.x + p10), rna_tf32(q.y - kb.y + p11));
                U[mt][nt][0] = va.x + p00;  U[mt][nt][1] = va.y + p01;
                U[mt][nt][2] = vb.x + p10;  U[mt][nt][3] = vb.y + p11;
            }
        }
    }
    __syncthreads();

    // ---- stage 2: h2 = rna(relu(t @ Wa1^T)) ----
    run_stage(Wa1r, acc, sA, sB, tid, lane, w);
    __syncthreads();
    {
        const int r0b = lane >> 2;
        const int colb = w*32 + (lane & 3)*2;
        #pragma unroll
        for (int mt = 0; mt < 4; mt++) {
            int r0 = mt*16 + r0b, r1 = r0 + 8;
            #pragma unroll
            for (int nt = 0; nt < 4; nt++) {
                int col = colb + nt*8;
                *(float2*)(smemf + r0*APITCH + col) = make_float2(
                    rna_tf32(fmaxf(acc[mt][nt][0], 0.f)),
                    rna_tf32(fmaxf(acc[mt][nt][1], 0.f)));
                *(float2*)(smemf + r1*APITCH + col) = make_float2(
                    rna_tf32(fmaxf(acc[mt][nt][2], 0.f)),
                    rna_tf32(fmaxf(acc[mt][nt][3], 0.f)));
            }
        }
    }
    __syncthreads();

    // ---- stage 3: A = h2 @ Wa2^T; softmax over 16 rows per point; res out ----
    run_stage(Wa2r, acc, sA, sB, tid, lane, w);

    {
        const float sc = 0.0625f;           // 1/sqrt(256)
        const int colb = w*32 + (lane & 3)*2;
        #pragma unroll
        for (int mt = 0; mt < 4; mt++) {
            int pt = pbase + mt;
            #pragma unroll
            for (int nt = 0; nt < 4; nt++) {
                int col = colb + nt*8;
                float rout[2];
                #pragma unroll
                for (int p = 0; p < 2; p++) {
                    float x0 = acc[mt][nt][p]     * sc;
                    float x1 = acc[mt][nt][2 + p] * sc;
                    float mx = fmaxf(x0, x1);
                    #pragma unroll
                    for (int o = 4; o < 32; o <<= 1)
                        mx = fmaxf(mx, __shfl_xor_sync(0xffffffffu, mx, o));
                    float e0 = __expf(x0 - mx), e1 = __expf(x1 - mx);
                    float s = e0 + e1;
                    float ww = e0*U[mt][nt][p] + e1*U[mt][nt][2 + p];
                    #pragma unroll
                    for (int o = 4; o < 32; o <<= 1) {
                        s  += __shfl_xor_sync(0xffffffffu, s , o);
                        ww += __shfl_xor_sync(0xffffffffu, ww, o);
                    }
                    rout[p] = ww / s;
                }
                if (lane < 4)
                    *(float2*)&g_res[(size_t)pt*DM + col] = make_float2(rout[0], rout[1]);
            }
        }
    }
}

// ---------------- final: proj + LN + post + LN + residual (16 pts / block) -------
__global__ void __launch_bounds__(256) final_kernel(
    const float* __restrict__ features, const float* __restrict__ b_post,
    const float* __restrict__ gdm, const float* __restrict__ bdm,
    const float* __restrict__ gdp, const float* __restrict__ bdp,
    float* __restrict__ out)
{
    int p0 = blockIdx.x * 16;
    int f  = threadIdx.x;
    __shared__ __align__(16) float rstage[DM*20];
    __shared__ float obuf[16*260];

    #pragma unroll
    for (int i = 0; i < 16; i++)
        rstage[f*20 + i] = g_res[(size_t)(p0 + i)*DM + f];
    __syncthreads();

    float acc[16];
    #pragma unroll
    for (int k = 0; k < 16; k++) acc[k] = 0.f;
    gemv16<DM>(g_WprojT, rstage, f, acc);
    #pragma unroll
    for (int k = 0; k < 16; k++) obuf[k*260 + f] = acc[k];
    __syncthreads();

    int wid = f >> 5, lane = f & 31;
    #pragma unroll
    for (int pp = 0; pp < 2; pp++) {
        int p = wid*2 + pp;
        const float* row = &obuf[p*260];
        float v[8]; float s = 0.f, s2 = 0.f;
        #pragma unroll
        for (int i = 0; i < 8; i++) { float x = row[lane*8 + i]; v[i] = x; s += x; s2 += x*x; }
        warp_bfly2(s, s2);
        float mu  = s  * (1.f/DM);
        float var = s2 * (1.f/DM) - mu*mu;
        float rs  = rsqrtf(var + 1e-5f);
        #pragma unroll
        for (int i = 0; i < 8; i++) {
            int c = lane*8 + i;
            rstage[c*20 + p] = (v[i] - mu) * rs * gdm[c] + bdm[c];
        }
    }
    __syncthreads();

    int po = f & 63, pg = f >> 6;
    float a4x = b_post[po], a4y = a4x, a4z = a4x, a4w = a4x;
    #pragma unroll 4
    for (int j = 0; j < DM; j++) {
        float w = __ldg(&g_WpostT[j*DP + po]);
        float4 z4 = *reinterpret_cast<const float4*>(&rstage[j*20 + pg*4]);
        a4x = fmaf(w, z4.x, a4x); a4y = fmaf(w, z4.y, a4y);
        a4z = fmaf(w, z4.z, a4z); a4w = fmaf(w, z4.w, a4w);
    }
    __syncthreads();
    obuf[(pg*4 + 0)*68 + po] = a4x;
    obuf[(pg*4 + 1)*68 + po] = a4y;
    obuf[(pg*4 + 2)*68 + po] = a4z;
    obuf[(pg*4 + 3)*68 + po] = a4w;
    __syncthreads();

    #pragma unroll
    for (int pp = 0; pp < 2; pp++) {
        int p = wid*2 + pp;
        float x0 = obuf[p*68 + lane], x1 = obuf[p*68 + 32 + lane];
        float s = x0 + x1, s2 = x0*x0 + x1*x1;
        warp_bfly2(s, s2);
        float mu  = s  * (1.f/DP);
        float var = s2 * (1.f/DP) - mu*mu;
        float rs  = rsqrtf(var + 1e-5f);
        size_t base = (size_t)(p0 + p)*DP;
        out[base + lane]      = (x0 - mu)*rs*gdp[lane]      + bdp[lane]      + features[base + lane];
        out[base + 32 + lane] = (x1 - mu)*rs*gdp[32 + lane] + bdp[32 + lane] + features[base + 32 + lane];
    }
}

// ---------------- launch ----------------
extern "C" void kernel_launch(void* const* d_in, const int* in_sizes, int n_in,
                              void* d_out, int out_size)
{
    const float* xyz      = (const float*)d_in[0];
    const float* features = (const float*)d_in[1];
    const float* W_pre    = (const float*)d_in[2];
    const float* b_pre    = (const float*)d_in[3];
    const float* W_post   = (const float*)d_in[4];
    const float* b_post   = (const float*)d_in[5];
    const float* Wp1      = (const float*)d_in[6];
    const float* Wp2      = (const float*)d_in[7];
    const float* Wa1      = (const float*)d_in[8];
    const float* Wa2      = (const float*)d_in[9];
    const float* WQ       = (const float*)d_in[10];
    const float* WK       = (const float*)d_in[11];
    const float* WV       = (const float*)d_in[12];
    const float* Wproj    = (const float*)d_in[13];
    const float* g_dm     = (const float*)d_in[14];
    const float* b_dm     = (const float*)d_in[15];
    const float* g_dp     = (const float*)d_in[16];
    const float* b_dp     = (const float*)d_in[17];
    float* out = (float*)d_out;

    float *d_Wp2r, *d_Wa1r, *d_Wa2r;
    cudaGetSymbolAddress((void**)&d_Wp2r, g_Wp2r);
    cudaGetSymbolAddress((void**)&d_Wa1r, g_Wa1r);
    cudaGetSymbolAddress((void**)&d_Wa2r, g_Wa2r);

    cudaFuncSetAttribute(knn_kernel, cudaFuncAttributeMaxDynamicSharedMemorySize,
                         NN * (int)sizeof(float4));
    cudaFuncSetAttribute(mega_kernel, cudaFuncAttributeMaxDynamicSharedMemorySize,
                         MEGA_SMEM);

    prep_kernel<<<256, 256>>>(W_pre, WQ, WK, WV, Wproj, W_post, Wp2, Wa1, Wa2);
    knn_kernel<<<BB*(NN/256), 256, NN*sizeof(float4)>>>(xyz);
    qkv_kernel<<<NPTS/16, 256>>>(features, b_pre, g_dm, b_dm);

    mega_kernel<<<MTOT/64, 256, MEGA_SMEM>>>(xyz, Wp1, d_Wp2r, d_Wa1r, d_Wa2r);

    final_kernel<<<NPTS/16, 256>>>(features, b_post, g_dm, b_dm, g_dp, b_dp, out);
}

// round 6
// speedup vs baseline: 1.3254x; 1.3254x over previous
#include <cuda_runtime.h>
#include <cuda_fp16.h>
#include <cstddef>
#include <cstdint>

#define BB 4
#define NN 4096
#define KK 16
#define DP 64
#define DM 256
#define NPTS (BB*NN)
#define MTOT (NPTS*KK)

// ---------------- device-global scratch (no allocs allowed) ----------------
__device__ float g_WpreT[DP*DM];
__device__ float g_WQT  [DM*DM];
__device__ float g_WKT  [DM*DM];
__device__ float g_WVT  [DM*DM];
__device__ float g_WprojT[DM*DM];
__device__ float g_WpostT[DM*DP];
__device__ __half g_Wp2h[DM*DM];   // fp16, row-major [n][k]
__device__ __half g_Wa1h[DM*DM];
__device__ __half g_Wa2h[DM*DM];
__device__ float g_Q [NPTS*DM];
__device__ float g_Kf[NPTS*DM];
__device__ float g_Vf[NPTS*DM];
__device__ int   g_idx[NPTS*KK];
__device__ float g_res[(size_t)NPTS*DM];

// ---------------- helpers ----------------
__device__ __forceinline__ uint32_t smem_u32(const void* p) {
    uint32_t a;
    asm("{ .reg .u64 t; cvta.to.shared.u64 t, %1; cvt.u32.u64 %0, t; }" : "=r"(a) : "l"(p));
    return a;
}
#define CP16(dst, src) asm volatile("cp.async.cg.shared.global [%0], [%1], 16;" :: "r"(dst), "l"(src) : "memory")
#define CP_COMMIT()    asm volatile("cp.async.commit_group;" ::: "memory")
#define CP_WAIT1()     asm volatile("cp.async.wait_group 1;" ::: "memory")
#define CP_WAIT0()     asm volatile("cp.async.wait_group 0;" ::: "memory")
#define LDSM4(r0,r1,r2,r3,a) \
    asm volatile("ldmatrix.sync.aligned.m8n8.x4.shared.b16 {%0,%1,%2,%3}, [%4];" \
                 : "=r"(r0),"=r"(r1),"=r"(r2),"=r"(r3) : "r"(a))

__device__ __forceinline__ void mma16816(float* c, const uint32_t* a, uint32_t b0, uint32_t b1) {
    asm volatile("mma.sync.aligned.m16n8k16.row.col.f32.f16.f16.f32 "
        "{%0,%1,%2,%3}, {%4,%5,%6,%7}, {%8,%9}, {%0,%1,%2,%3};"
        : "+f"(c[0]), "+f"(c[1]), "+f"(c[2]), "+f"(c[3])
        : "r"(a[0]), "r"(a[1]), "r"(a[2]), "r"(a[3]), "r"(b0), "r"(b1));
}

// ---------------- weight prep ----------------
__global__ void prep_kernel(const float* __restrict__ W_pre,
                            const float* __restrict__ WQ,  const float* __restrict__ WK,
                            const float* __restrict__ WV,  const float* __restrict__ Wproj,
                            const float* __restrict__ W_post,
                            const float* __restrict__ Wp2, const float* __restrict__ Wa1,
                            const float* __restrict__ Wa2)
{
    int t = blockIdx.x * blockDim.x + threadIdx.x;
    if (t < DM*DP) {
        int fo = t >> 6, j = t & 63;
        g_WpreT[j*DM + fo] = W_pre[t];
    }
    if (t < DP*DM) {
        int p = t >> 8, j = t & 255;
        g_WpostT[j*DP + p] = W_post[t];
    }
    if (t < DM*DM) {
        int r = t >> 8, c = t & 255;
        g_WQT   [c*DM + r] = WQ[t];
        g_WKT   [c*DM + r] = WK[t];
        g_WVT   [c*DM + r] = WV[t];
        g_WprojT[c*DM + r] = Wproj[t];
        g_Wp2h[t] = __float2half_rn(Wp2[t]);
        g_Wa1h[t] = __float2half_rn(Wa1[t]);
        g_Wa2h[t] = __float2half_rn(Wa2[t]);
    }
}

// ---------------- kNN ----------------
__global__ void __launch_bounds__(256) knn_kernel(const float* __restrict__ xyz)
{
    extern __shared__ float4 pts[];
    int b     = blockIdx.x >> 4;
    int chunk = blockIdx.x & 15;
    const float* xb = xyz + (size_t)b * NN * 3;
    for (int m = threadIdx.x; m < NN; m += 256)
        pts[m] = make_float4(xb[m*3], xb[m*3+1], xb[m*3+2], 0.f);
    __syncthreads();

    int qi = chunk * 256 + threadIdx.x;
    float4 qp = pts[qi];

    float bd[KK]; int bi[KK];
    #pragma unroll
    for (int i = 0; i < KK; i++) { bd[i] = 3.4e38f; bi[i] = i; }
    float worst = 3.4e38f; int wpos = 0;

    for (int m = 0; m < NN; m++) {
        float4 p = pts[m];
        float dx = qp.x - p.x, dy = qp.y - p.y, dz = qp.z - p.z;
        float d = fmaf(dx, dx, fmaf(dy, dy, dz * dz));
        if (d < worst) {
            bd[wpos] = d; bi[wpos] = m;
            worst = bd[0]; wpos = 0;
            #pragma unroll
            for (int i = 1; i < KK; i++)
                if (bd[i] > worst) { worst = bd[i]; wpos = i; }
        }
    }
    #pragma unroll
    for (int i = 0; i < KK; i++)
        g_idx[(size_t)(b*NN + qi)*KK + i] = bi[i];
}

// ---------------- SIMT gemv helpers (qkv + final) ----------------
template<int LEN>
__device__ __forceinline__ void gemv16(const float* __restrict__ WT,
                                       const float* __restrict__ hb,
                                       int f, float* acc)
{
    #pragma unroll 4
    for (int j = 0; j < LEN; j++) {
        float w = __ldg(&WT[j*DM + f]);
        const float4* hr = reinterpret_cast<const float4*>(hb + j*20);
        float4 h0 = hr[0], h1 = hr[1], h2 = hr[2], h3 = hr[3];
        acc[0]  = fmaf(w, h0.x, acc[0]);  acc[1]  = fmaf(w, h0.y, acc[1]);
        acc[2]  = fmaf(w, h0.z, acc[2]);  acc[3]  = fmaf(w, h0.w, acc[3]);
        acc[4]  = fmaf(w, h1.x, acc[4]);  acc[5]  = fmaf(w, h1.y, acc[5]);
        acc[6]  = fmaf(w, h1.z, acc[6]);  acc[7]  = fmaf(w, h1.w, acc[7]);
        acc[8]  = fmaf(w, h2.x, acc[8]);  acc[9]  = fmaf(w, h2.y, acc[9]);
        acc[10] = fmaf(w, h2.z, acc[10]); acc[11] = fmaf(w, h2.w, acc[11]);
        acc[12] = fmaf(w, h3.x, acc[12]); acc[13] = fmaf(w, h3.y, acc[13]);
        acc[14] = fmaf(w, h3.z, acc[14]); acc[15] = fmaf(w, h3.w, acc[15]);
    }
}

__device__ __forceinline__ void warp_bfly2(float& s, float& s2)
{
    #pragma unroll
    for (int o = 16; o; o >>= 1) {
        s  += __shfl_xor_sync(0xffffffffu, s , o);
        s2 += __shfl_xor_sync(0xffffffffu, s2, o);
    }
}

__device__ __forceinline__ void qkv_proj(const float* __restrict__ WT,
    const float* __restrict__ ibuf, float* obuf,
    const float* __restrict__ gg, const float* __restrict__ bb,
    float* __restrict__ outg, int f)
{
    float acc[16];
    #pragma unroll
    for (int k = 0; k < 16; k++) acc[k] = 0.f;
    gemv16<DM>(WT, ibuf, f, acc);
    #pragma unroll
    for (int k = 0; k < 16; k++) obuf[k*260 + f] = acc[k];
    __syncthreads();

    int wid = f >> 5, lane = f & 31;
    #pragma unroll
    for (int pp = 0; pp < 2; pp++) {
        int p = wid*2 + pp;
        const float* row = &obuf[p*260];
        float v[8]; float s = 0.f, s2 = 0.f;
        #pragma unroll
        for (int i = 0; i < 8; i++) { float x = row[lane*8 + i]; v[i] = x; s += x; s2 += x*x; }
        warp_bfly2(s, s2);
        float mu  = s  * (1.f/DM);
        float var = s2 * (1.f/DM) - mu*mu;
        float rs  = rsqrtf(var + 1e-5f);
        #pragma unroll
        for (int i = 0; i < 8; i++) {
            int c = lane*8 + i;
            outg[(size_t)p*DM + c] = (v[i] - mu) * rs * gg[c] + bb[c];
        }
    }
    __syncthreads();
}

__global__ void __launch_bounds__(256) qkv_kernel(
    const float* __restrict__ features, const float* __restrict__ b_pre,
    const float* __restrict__ gdm, const float* __restrict__ bdm)
{
    int p0 = blockIdx.x * 16;
    int f  = threadIdx.x;
    __shared__ __align__(16) float featsm[DP*20];
    __shared__ __align__(16) float ibuf  [DM*20];
    __shared__ float obuf[16*260];

    for (int t = f; t < 16*DP; t += 256) {
        int p = t >> 6, j = t & 63;
        featsm[j*20 + p] = features[(size_t)(p0 + p)*DP + j];
    }
    __syncthreads();

    float acc[16];
    float bp = b_pre[f];
    #pragma unroll
    for (int k = 0; k < 16; k++) acc[k] = bp;
    gemv16<DP>(g_WpreT, featsm, f, acc);
    #pragma unroll
    for (int k = 0; k < 16; k++) ibuf[f*20 + k] = acc[k];
    __syncthreads();

    qkv_proj(g_WQT, ibuf, obuf, gdm, bdm, g_Q  + (size_t)p0*DM, f);
    qkv_proj(g_WKT, ibuf, obuf, gdm, bdm, g_Kf + (size_t)p0*DM, f);
    qkv_proj(g_WVT, ibuf, obuf, gdm, bdm, g_Vf + (size_t)p0*DM, f);
}

// ---------------- fused mega-kernel (fp16 MMA, 512 threads) ----------------
// 64 rows (4 points) x 256 cols per CTA. 16 warps: wn = w&7 (32-col slice),
// wm2 = w>>3 (32-row slice -> 2 m16 tiles). acc[2][4][4].
// A: 64 rows x 528 B pitch fp16 (33792 B). B chunks: 256 rows x 144 B (64 k-halves),
// double buffered (2 x 36864 B). Total smem 107520 B.
#define APITCH_B 528
#define ABYTES   (64*APITCH_B)           // 33792
#define BBYTES   (256*144)               // 36864
#define MEGA_SMEM (ABYTES + 2*BBYTES)    // 107520

__device__ __forceinline__ void load_bchunk(uint32_t sB, const __half* __restrict__ W,
                                            int kt, int buf, int tid)
{
    uint32_t base = sB + (uint32_t)buf*BBYTES;
    #pragma unroll
    for (int i = 0; i < 4; i++) {
        int ch = tid + i*512;
        int r = ch >> 3, c = ch & 7;
        CP16(base + r*144 + c*16, W + (size_t)r*256 + kt*64 + c*8);
    }
}

template<bool FINAL>
__device__ __forceinline__ void run_stage(const __half* __restrict__ Bw,
                                          const __half* __restrict__ nextBw,
                                          float acc[2][4][4],
                                          uint32_t sA, uint32_t sB,
                                          int tid, int lane, int wn, int wm2)
{
    #pragma unroll
    for (int mt = 0; mt < 2; mt++)
        #pragma unroll
        for (int nt = 0; nt < 4; nt++)
            #pragma unroll
            for (int j = 0; j < 4; j++) acc[mt][nt][j] = 0.f;

    const uint32_t aAddr = sA + (uint32_t)(wm2*32 + (lane & 15))*APITCH_B + (lane >> 4)*16;
    const uint32_t bAddr = sB + (uint32_t)(wn*32 + ((lane >> 4) & 1)*8 + (lane & 7))*144
                              + ((lane >> 3) & 1)*16;

    for (int kt = 0; kt < 4; kt++) {
        if (FINAL && kt == 3) { CP_WAIT0(); } else { CP_WAIT1(); }
        __syncthreads();

        uint32_t ab = aAddr + kt*128;
        uint32_t bb = bAddr + (uint32_t)(kt & 1)*BBYTES;
        #pragma unroll
        for (int ks = 0; ks < 4; ks++) {
            uint32_t af[2][4], bf[2][4];
            LDSM4(af[0][0], af[0][1], af[0][2], af[0][3], ab + ks*32);
            LDSM4(af[1][0], af[1][1], af[1][2], af[1][3], ab + 16*APITCH_B + ks*32);
            LDSM4(bf[0][0], bf[0][1], bf[0][2], bf[0][3], bb + ks*32);
            LDSM4(bf[1][0], bf[1][1], bf[1][2], bf[1][3], bb + 16*144 + ks*32);
            #pragma unroll
            for (int mt = 0; mt < 2; mt++)
                #pragma unroll
                for (int nt = 0; nt < 4; nt++)
                    mma16816(acc[mt][nt], af[mt],
                             bf[nt >> 1][(nt & 1)*2], bf[nt >> 1][(nt & 1)*2 + 1]);
        }
        __syncthreads();

        int ci = kt + 2;
        if (ci < 4)        { load_bchunk(sB, Bw,     ci,     kt & 1, tid); CP_COMMIT(); }
        else if (nextBw)   { load_bchunk(sB, nextBw, ci - 4, kt & 1, tid); CP_COMMIT(); }
    }
}

__global__ void __launch_bounds__(512) mega_kernel(
    const float* __restrict__ xyz, const float* __restrict__ Wp1,
    const __half* __restrict__ Wp2h, const __half* __restrict__ Wa1h,
    const __half* __restrict__ Wa2h)
{
    extern __shared__ char smemc[];
    uint32_t sA = smem_u32(smemc);
    uint32_t sB = sA + ABYTES;

    const int tid  = threadIdx.x;
    const int lane = tid & 31, w = tid >> 5;
    const int wn = w & 7, wm2 = w >> 3;
    const int m0    = blockIdx.x * 64;
    const int pbase = m0 >> 4;
    const int bq    = pbase >> 12;

    __shared__ float rel3[64][3];
    __shared__ int   idxs[64];

    // kick off first two weight chunks immediately
    load_bchunk(sB, Wp2h, 0, 0, tid); CP_COMMIT();
    load_bchunk(sB, Wp2h, 1, 1, tid); CP_COMMIT();

    // ---- prologue: rel + neighbor ids ----
    if (tid < 64) {
        int m  = m0 + tid;
        int pt = m >> 4;
        int n  = pt & (NN - 1);
        int id = g_idx[(size_t)pt*KK + (m & 15)];
        idxs[tid] = id;
        const float* xb = xyz + (size_t)bq*NN*3;
        rel3[tid][0] = xb[n*3 + 0] - xb[id*3 + 0];
        rel3[tid][1] = xb[n*3 + 1] - xb[id*3 + 1];
        rel3[tid][2] = xb[n*3 + 2] - xb[id*3 + 2];
    }
    __syncthreads();

    // ---- h1 = relu(rel @ Wp1^T) -> fp16 A buffer ----
    {
        int c0 = (tid & 127)*2;
        int j0 = (tid >> 7)*16;
        float a0 = Wp1[c0*3+0], a1 = Wp1[c0*3+1], a2 = Wp1[c0*3+2];
        float d0 = Wp1[c0*3+3], d1 = Wp1[c0*3+4], d2 = Wp1[c0*3+5];
        #pragma unroll
        for (int j = j0; j < j0 + 16; j++) {
            float h0 = fmaf(a0, rel3[j][0], fmaf(a1, rel3[j][1], a2*rel3[j][2]));
            float h1 = fmaf(d0, rel3[j][0], fmaf(d1, rel3[j][1], d2*rel3[j][2]));
            *(half2*)(smemc + (size_t)j*APITCH_B + c0*2) =
                __floats2half2_rn(fmaxf(h0, 0.f), fmaxf(h1, 0.f));
        }
    }
    // (visibility to LDSM guaranteed by the __syncthreads inside run_stage)

    float acc[2][4][4];
    float U[2][4][4];

    // ---- stage 1: pos = h1 @ Wp2^T ----
    run_stage<false>(Wp2h, Wa1h, acc, sA, sB, tid, lane, wn, wm2);

    // epilogue 1: t = fp16(q - k + pos) -> A; U = v + pos -> regs
    {
        const int r0b  = lane >> 2;
        const int colb = wn*32 + (lane & 3)*2;
        #pragma unroll
        for (int mt = 0; mt < 2; mt++) {
            int gmt = wm2*2 + mt;
            int pt  = pbase + gmt;
            int r0  = gmt*16 + r0b, r1 = r0 + 8;
            const float* qp  = g_Q  + (size_t)pt*DM;
            const float* k0p = g_Kf + ((size_t)(bq << 12) + idxs[r0])*DM;
            const float* k1p = g_Kf + ((size_t)(bq << 12) + idxs[r1])*DM;
            const float* v0p = g_Vf + ((size_t)(bq << 12) + idxs[r0])*DM;
            const float* v1p = g_Vf + ((size_t)(bq << 12) + idxs[r1])*DM;
            #pragma unroll
            for (int nt = 0; nt < 4; nt++) {
                int col = colb + nt*8;
                float2 q  = *(const float2*)(qp  + col);
                float2 ka = *(const float2*)(k0p + col);
                float2 kb = *(const float2*)(k1p + col);
                float2 va = *(const float2*)(v0p + col);
                float2 vb = *(const float2*)(v1p + col);
                float p00 = acc[mt][nt][0], p01 = acc[mt][nt][1];
                float p10 = acc[mt][nt][2], p11 = acc[mt][nt][3];
                *(half2*)(smemc + (size_t)r0*APITCH_B + col*2) =
                    __floats2half2_rn(q.x - ka.x + p00, q.y - ka.y + p01);
                *(half2*)(smemc + (size_t)r1*APITCH_B + col*2) =
                    __floats2half2_rn(q.x - kb.x + p10, q.y - kb.y + p11);
                U[mt][nt][0] = va.x + p00;  U[mt][nt][1] = va.y + p01;
                U[mt][nt][2] = vb.x + p10;  U[mt][nt][3] = vb.y + p11;
            }
        }
    }

    // ---- stage 2: h2 = relu(t @ Wa1^T) ----
    run_stage<false>(Wa1h, Wa2h, acc, sA, sB, tid, lane, wn, wm2);
    {
        const int r0b  = lane >> 2;
        const int colb = wn*32 + (lane & 3)*2;
        #pragma unroll
        for (int mt = 0; mt < 2; mt++) {
            int gmt = wm2*2 + mt;
            int r0  = gmt*16 + r0b, r1 = r0 + 8;
            #pragma unroll
            for (int nt = 0; nt < 4; nt++) {
                int col = colb + nt*8;
                *(half2*)(smemc + (size_t)r0*APITCH_B + col*2) =
                    __floats2half2_rn(fmaxf(acc[mt][nt][0], 0.f), fmaxf(acc[mt][nt][1], 0.f));
                *(half2*)(smemc + (size_t)r1*APITCH_B + col*2) =
                    __floats2half2_rn(fmaxf(acc[mt][nt][2], 0.f), fmaxf(acc[mt][nt][3], 0.f));
            }
        }
    }

    // ---- stage 3: A = h2 @ Wa2^T; softmax over 16 rows/point; write res ----
    run_stage<true>(Wa2h, nullptr, acc, sA, sB, tid, lane, wn, wm2);
    {
        const float sc = 0.0625f;           // 1/sqrt(256)
        const int colb = wn*32 + (lane & 3)*2;
        #pragma unroll
        for (int mt = 0; mt < 2; mt++) {
            int pt = pbase + wm2*2 + mt;
            #pragma unroll
            for (int nt = 0; nt < 4; nt++) {
                int col = colb + nt*8;
                float rout[2];
                #pragma unroll
                for (int p = 0; p < 2; p++) {
                    float x0 = acc[mt][nt][p]     * sc;
                    float x1 = acc[mt][nt][2 + p] * sc;
                    float mx = fmaxf(x0, x1);
                    #pragma unroll
                    for (int o = 4; o < 32; o <<= 1)
                        mx = fmaxf(mx, __shfl_xor_sync(0xffffffffu, mx, o));
                    float e0 = __expf(x0 - mx), e1 = __expf(x1 - mx);
                    float s  = e0 + e1;
                    float ww = e0*U[mt][nt][p] + e1*U[mt][nt][2 + p];
                    #pragma unroll
                    for (int o = 4; o < 32; o <<= 1) {
                        s  += __shfl_xor_sync(0xffffffffu, s , o);
                        ww += __shfl_xor_sync(0xffffffffu, ww, o);
                    }
                    rout[p] = ww / s;
                }
                if (lane < 4)
                    *(float2*)&g_res[(size_t)pt*DM + col] = make_float2(rout[0], rout[1]);
            }
        }
    }
}

// ---------------- final: proj + LN + post + LN + residual (16 pts / block) -------
__global__ void __launch_bounds__(256) final_kernel(
    const float* __restrict__ features, const float* __restrict__ b_post,
    const float* __restrict__ gdm, const float* __restrict__ bdm,
    const float* __restrict__ gdp, const float* __restrict__ bdp,
    float* __restrict__ out)
{
    int p0 = blockIdx.x * 16;
    int f  = threadIdx.x;
    __shared__ __align__(16) float rstage[DM*20];
    __shared__ float obuf[16*260];

    #pragma unroll
    for (int i = 0; i < 16; i++)
        rstage[f*20 + i] = g_res[(size_t)(p0 + i)*DM + f];
    __syncthreads();

    float acc[16];
    #pragma unroll
    for (int k = 0; k < 16; k++) acc[k] = 0.f;
    gemv16<DM>(g_WprojT, rstage, f, acc);
    #pragma unroll
    for (int k = 0; k < 16; k++) obuf[k*260 + f] = acc[k];
    __syncthreads();

    int wid = f >> 5, lane = f & 31;
    #pragma unroll
    for (int pp = 0; pp < 2; pp++) {
        int p = wid*2 + pp;
        const float* row = &obuf[p*260];
        float v[8]; float s = 0.f, s2 = 0.f;
        #pragma unroll
        for (int i = 0; i < 8; i++) { float x = row[lane*8 + i]; v[i] = x; s += x; s2 += x*x; }
        warp_bfly2(s, s2);
        float mu  = s  * (1.f/DM);
        float var = s2 * (1.f/DM) - mu*mu;
        float rs  = rsqrtf(var + 1e-5f);
        #pragma unroll
        for (int i = 0; i < 8; i++) {
            int c = lane*8 + i;
            rstage[c*20 + p] = (v[i] - mu) * rs * gdm[c] + bdm[c];
        }
    }
    __syncthreads();

    int po = f & 63, pg = f >> 6;
    float a4x = b_post[po], a4y = a4x, a4z = a4x, a4w = a4x;
    #pragma unroll 4
    for (int j = 0; j < DM; j++) {
        float w = __ldg(&g_WpostT[j*DP + po]);
        float4 z4 = *reinterpret_cast<const float4*>(&rstage[j*20 + pg*4]);
        a4x = fmaf(w, z4.x, a4x); a4y = fmaf(w, z4.y, a4y);
        a4z = fmaf(w, z4.z, a4z); a4w = fmaf(w, z4.w, a4w);
    }
    __syncthreads();
    obuf[(pg*4 + 0)*68 + po] = a4x;
    obuf[(pg*4 + 1)*68 + po] = a4y;
    obuf[(pg*4 + 2)*68 + po] = a4z;
    obuf[(pg*4 + 3)*68 + po] = a4w;
    __syncthreads();

    #pragma unroll
    for (int pp = 0; pp < 2; pp++) {
        int p = wid*2 + pp;
        float x0 = obuf[p*68 + lane], x1 = obuf[p*68 + 32 + lane];
        float s = x0 + x1, s2 = x0*x0 + x1*x1;
        warp_bfly2(s, s2);
        float mu  = s  * (1.f/DP);
        float var = s2 * (1.f/DP) - mu*mu;
        float rs  = rsqrtf(var + 1e-5f);
        size_t base = (size_t)(p0 + p)*DP;
        out[base + lane]      = (x0 - mu)*rs*gdp[lane]      + bdp[lane]      + features[base + lane];
        out[base + 32 + lane] = (x1 - mu)*rs*gdp[32 + lane] + bdp[32 + lane] + features[base + 32 + lane];
    }
}

// ---------------- launch ----------------
extern "C" void kernel_launch(void* const* d_in, const int* in_sizes, int n_in,
                              void* d_out, int out_size)
{
    const float* xyz      = (const float*)d_in[0];
    const float* features = (const float*)d_in[1];
    const float* W_pre    = (const float*)d_in[2];
    const float* b_pre    = (const float*)d_in[3];
    const float* W_post   = (const float*)d_in[4];
    const float* b_post   = (const float*)d_in[5];
    const float* Wp1      = (const float*)d_in[6];
    const float* Wp2      = (const float*)d_in[7];
    const float* Wa1      = (const float*)d_in[8];
    const float* Wa2      = (const float*)d_in[9];
    const float* WQ       = (const float*)d_in[10];
    const float* WK       = (const float*)d_in[11];
    const float* WV       = (const float*)d_in[12];
    const float* Wproj    = (const float*)d_in[13];
    const float* g_dm     = (const float*)d_in[14];
    const float* b_dm     = (const float*)d_in[15];
    const float* g_dp     = (const float*)d_in[16];
    const float* b_dp     = (const float*)d_in[17];
    float* out = (float*)d_out;

    __half *d_Wp2h, *d_Wa1h, *d_Wa2h;
    cudaGetSymbolAddress((void**)&d_Wp2h, g_Wp2h);
    cudaGetSymbolAddress((void**)&d_Wa1h, g_Wa1h);
    cudaGetSymbolAddress((void**)&d_Wa2h, g_Wa2h);

    cudaFuncSetAttribute(knn_kernel, cudaFuncAttributeMaxDynamicSharedMemorySize,
                         NN * (int)sizeof(float4));
    cudaFuncSetAttribute(mega_kernel, cudaFuncAttributeMaxDynamicSharedMemorySize,
                         MEGA_SMEM);

    prep_kernel<<<256, 256>>>(W_pre, WQ, WK, WV, Wproj, W_post, Wp2, Wa1, Wa2);
    knn_kernel<<<BB*(NN/256), 256, NN*sizeof(float4)>>>(xyz);
    qkv_kernel<<<NPTS/16, 256>>>(features, b_pre, g_dm, b_dm);

    mega_kernel<<<MTOT/64, 512, MEGA_SMEM>>>(xyz, Wp1, d_Wp2h, d_Wa1h, d_Wa2h);

    final_kernel<<<NPTS/16, 256>>>(features, b_post, g_dm, b_dm, g_dp, b_dp, out);
}

// round 7
// speedup vs baseline: 1.6605x; 1.2528x over previous
#include <cuda_runtime.h>
#include <cuda_fp16.h>
#include <cstddef>
#include <cstdint>

#define BB 4
#define NN 4096
#define KK 16
#define DP 64
#define DM 256
#define NPTS (BB*NN)
#define MTOT (NPTS*KK)

// ---------------- device-global scratch (no allocs allowed) ----------------
__device__ float  g_WpostT[DM*DP];   // [j][p] fp32
__device__ __half g_Wpreh[DM*DP];    // [n=256][k=64]
__device__ __half g_WQh [DM*DM];     // [n][k]
__device__ __half g_WKh [DM*DM];
__device__ __half g_WVh [DM*DM];
__device__ __half g_Wprojh[DM*DM];
__device__ __half g_Wp2h[DM*DM];
__device__ __half g_Wa1h[DM*DM];
__device__ __half g_Wa2h[DM*DM];
__device__ float g_Q [NPTS*DM];
__device__ float g_Kf[NPTS*DM];
__device__ float g_Vf[NPTS*DM];
__device__ int   g_idx[NPTS*KK];
__device__ float g_res[(size_t)NPTS*DM];

// ---------------- helpers ----------------
__device__ __forceinline__ uint32_t smem_u32(const void* p) {
    uint32_t a;
    asm("{ .reg .u64 t; cvta.to.shared.u64 t, %1; cvt.u32.u64 %0, t; }" : "=r"(a) : "l"(p));
    return a;
}
#define CP16(dst, src) asm volatile("cp.async.cg.shared.global [%0], [%1], 16;" :: "r"(dst), "l"(src) : "memory")
#define CP_COMMIT()    asm volatile("cp.async.commit_group;" ::: "memory")
#define CP_WAIT1()     asm volatile("cp.async.wait_group 1;" ::: "memory")
#define CP_WAIT0()     asm volatile("cp.async.wait_group 0;" ::: "memory")
#define LDSM4(r0,r1,r2,r3,a) \
    asm volatile("ldmatrix.sync.aligned.m8n8.x4.shared.b16 {%0,%1,%2,%3}, [%4];" \
                 : "=r"(r0),"=r"(r1),"=r"(r2),"=r"(r3) : "r"(a))

__device__ __forceinline__ void mma16816(float* c, const uint32_t* a, uint32_t b0, uint32_t b1) {
    asm volatile("mma.sync.aligned.m16n8k16.row.col.f32.f16.f16.f32 "
        "{%0,%1,%2,%3}, {%4,%5,%6,%7}, {%8,%9}, {%0,%1,%2,%3};"
        : "+f"(c[0]), "+f"(c[1]), "+f"(c[2]), "+f"(c[3])
        : "r"(a[0]), "r"(a[1]), "r"(a[2]), "r"(a[3]), "r"(b0), "r"(b1));
}

#define APITCH_B 528
#define ABYTES   (64*APITCH_B)           // 33792
#define BBYTES   (256*144)               // 36864
#define MEGA_SMEM (ABYTES + 2*BBYTES)    // 107520

// shared inner MMA tile: 2 A-frag groups x 2 B-frag groups x 4 ks
__device__ __forceinline__ void mma_tile(uint32_t ab, uint32_t bb, float acc[2][4][4])
{
    #pragma unroll
    for (int ks = 0; ks < 4; ks++) {
        uint32_t af[2][4], bf[2][4];
        LDSM4(af[0][0], af[0][1], af[0][2], af[0][3], ab + ks*32);
        LDSM4(af[1][0], af[1][1], af[1][2], af[1][3], ab + 16*APITCH_B + ks*32);
        LDSM4(bf[0][0], bf[0][1], bf[0][2], bf[0][3], bb + ks*32);
        LDSM4(bf[1][0], bf[1][1], bf[1][2], bf[1][3], bb + 16*144 + ks*32);
        #pragma unroll
        for (int mt = 0; mt < 2; mt++)
            #pragma unroll
            for (int nt = 0; nt < 4; nt++)
                mma16816(acc[mt][nt], af[mt],
                         bf[nt >> 1][(nt & 1)*2], bf[nt >> 1][(nt & 1)*2 + 1]);
    }
}

__device__ __forceinline__ void load_w256(uint32_t sB, const __half* __restrict__ W,
                                          int kt, int buf, int tid)
{
    uint32_t base = sB + (uint32_t)buf*BBYTES;
    #pragma unroll
    for (int i = 0; i < 4; i++) {
        int ch = tid + i*512;
        int r = ch >> 3, c = ch & 7;
        CP16(base + r*144 + c*16, W + (size_t)r*256 + kt*64 + c*8);
    }
}

__device__ __forceinline__ void zero_acc(float acc[2][4][4])
{
    #pragma unroll
    for (int mt = 0; mt < 2; mt++)
        #pragma unroll
        for (int nt = 0; nt < 4; nt++)
            #pragma unroll
            for (int j = 0; j < 4; j++) acc[mt][nt][j] = 0.f;
}

__device__ __forceinline__ void warp_bfly2(float& s, float& s2)
{
    #pragma unroll
    for (int o = 16; o; o >>= 1) {
        s  += __shfl_xor_sync(0xffffffffu, s , o);
        s2 += __shfl_xor_sync(0xffffffffu, s2, o);
    }
}

// ---------------- weight prep ----------------
__global__ void prep_kernel(const float* __restrict__ W_pre,
                            const float* __restrict__ WQ,  const float* __restrict__ WK,
                            const float* __restrict__ WV,  const float* __restrict__ Wproj,
                            const float* __restrict__ W_post,
                            const float* __restrict__ Wp2, const float* __restrict__ Wa1,
                            const float* __restrict__ Wa2)
{
    int t = blockIdx.x * blockDim.x + threadIdx.x;
    if (t < DM*DP) {
        g_Wpreh[t] = __float2half_rn(W_pre[t]);
        int p = t >> 8, j = t & 255;          // W_post [64][256]
        g_WpostT[j*DP + p] = W_post[t];
    }
    if (t < DM*DM) {
        g_WQh  [t] = __float2half_rn(WQ[t]);
        g_WKh  [t] = __float2half_rn(WK[t]);
        g_WVh  [t] = __float2half_rn(WV[t]);
        g_Wprojh[t] = __float2half_rn(Wproj[t]);
        g_Wp2h[t] = __float2half_rn(Wp2[t]);
        g_Wa1h[t] = __float2half_rn(Wa1[t]);
        g_Wa2h[t] = __float2half_rn(Wa2[t]);
    }
}

// ---------------- kNN ----------------
__global__ void __launch_bounds__(256) knn_kernel(const float* __restrict__ xyz)
{
    extern __shared__ float4 pts[];
    int b     = blockIdx.x >> 4;
    int chunk = blockIdx.x & 15;
    const float* xb = xyz + (size_t)b * NN * 3;
    for (int m = threadIdx.x; m < NN; m += 256)
        pts[m] = make_float4(xb[m*3], xb[m*3+1], xb[m*3+2], 0.f);
    __syncthreads();

    int qi = chunk * 256 + threadIdx.x;
    float4 qp = pts[qi];

    float bd[KK]; int bi[KK];
    #pragma unroll
    for (int i = 0; i < KK; i++) { bd[i] = 3.4e38f; bi[i] = i; }
    float worst = 3.4e38f; int wpos = 0;

    for (int m = 0; m < NN; m++) {
        float4 p = pts[m];
        float dx = qp.x - p.x, dy = qp.y - p.y, dz = qp.z - p.z;
        float d = fmaf(dx, dx, fmaf(dy, dy, dz * dz));
        if (d < worst) {
            bd[wpos] = d; bi[wpos] = m;
            worst = bd[0]; wpos = 0;
            #pragma unroll
            for (int i = 1; i < KK; i++)
                if (bd[i] > worst) { worst = bd[i]; wpos = i; }
        }
    }
    #pragma unroll
    for (int i = 0; i < KK; i++)
        g_idx[(size_t)(b*NN + qi)*KK + i] = bi[i];
}

// ---------------- LN epilogue (row-wise over 256 cols) -> fp32 gmem ----------------
__device__ __forceinline__ void ln_reduce(float acc[2][4][4], float2 (*red)[8],
                                          int lane, int wn, int wm2)
{
    #pragma unroll
    for (int mt = 0; mt < 2; mt++) {
        int gmt = wm2*2 + mt;
        int r0 = gmt*16 + (lane >> 2), r1 = r0 + 8;
        float s0=0.f, q0=0.f, s1=0.f, q1=0.f;
        #pragma unroll
        for (int nt = 0; nt < 4; nt++) {
            float a0=acc[mt][nt][0], a1=acc[mt][nt][1];
            float a2=acc[mt][nt][2], a3=acc[mt][nt][3];
            s0 += a0+a1; q0 += a0*a0+a1*a1;
            s1 += a2+a3; q1 += a2*a2+a3*a3;
        }
        #pragma unroll
        for (int o = 1; o < 4; o <<= 1) {
            s0 += __shfl_xor_sync(~0u, s0, o); q0 += __shfl_xor_sync(~0u, q0, o);
            s1 += __shfl_xor_sync(~0u, s1, o); q1 += __shfl_xor_sync(~0u, q1, o);
        }
        if ((lane & 3) == 0) {
            red[r0][wn] = make_float2(s0, q0);
            red[r1][wn] = make_float2(s1, q1);
        }
    }
    __syncthreads();
}

__device__ __forceinline__ void ln_stats(float2 (*red)[8], int row, float& mu, float& rs)
{
    float S = 0.f, Q = 0.f;
    #pragma unroll
    for (int i = 0; i < 8; i++) { float2 e = red[row][i]; S += e.x; Q += e.y; }
    mu = S * (1.f/DM);
    float var = Q * (1.f/DM) - mu*mu;
    rs = rsqrtf(var + 1e-5f);
}

// ---------------- qkv via HMMA: inp -> Q/K/V with fused LN ----------------
__global__ void __launch_bounds__(512) qkvmma_kernel(
    const float* __restrict__ features, const float* __restrict__ b_pre,
    const float* __restrict__ gdm, const float* __restrict__ bdm)
{
    extern __shared__ char smemc[];
    __shared__ float2 red[64][8];
    uint32_t sA = smem_u32(smemc);
    uint32_t sB = sA + ABYTES;
    const int tid = threadIdx.x, lane = tid & 31, w = tid >> 5;
    const int wn = w & 7, wm2 = w >> 3;
    const int p0 = blockIdx.x * 64;

    // chunk0 = Wpre (rowstride 64), chunk1 = WQ kt0
    {
        #pragma unroll
        for (int i = 0; i < 4; i++) {
            int ch = tid + i*512; int r = ch >> 3, c = ch & 7;
            CP16(sB + r*144 + c*16, g_Wpreh + r*64 + c*8);
        }
        CP_COMMIT();
        load_w256(sB, g_WQh, 0, 1, tid); CP_COMMIT();
    }

    // features -> A fp16 (64 rows x 64 k)
    for (int ch = tid; ch < 64*32; ch += 512) {
        int r = ch >> 5, c2 = ch & 31;
        float2 v = *(const float2*)&features[(size_t)(p0 + r)*DP + c2*2];
        *(half2*)(smemc + (size_t)r*APITCH_B + c2*4) = __floats2half2_rn(v.x, v.y);
    }

    const uint32_t aAddr = sA + (uint32_t)(wm2*32 + (lane & 15))*APITCH_B + (lane >> 4)*16;
    const uint32_t bAddr = sB + (uint32_t)(wn*32 + ((lane >> 4) & 1)*8 + (lane & 7))*144
                              + ((lane >> 3) & 1)*16;

    float acc[2][4][4];

    // ---- stage 0: inp = feat @ Wpre^T + b_pre (K=64, chunk0) ----
    zero_acc(acc);
    CP_WAIT1(); __syncthreads();
    mma_tile(aAddr, bAddr, acc);
    __syncthreads();
    load_w256(sB, g_WQh, 1, 0, tid); CP_COMMIT();   // chunk2
    {
        #pragma unroll
        for (int mt = 0; mt < 2; mt++) {
            int gmt = wm2*2 + mt;
            int r0 = gmt*16 + (lane >> 2), r1 = r0 + 8;
            #pragma unroll
            for (int nt = 0; nt < 4; nt++) {
                int col = wn*32 + nt*8 + (lane & 3)*2;
                float b0 = b_pre[col], b1 = b_pre[col+1];
                *(half2*)(smemc + (size_t)r0*APITCH_B + col*2) =
                    __floats2half2_rn(acc[mt][nt][0] + b0, acc[mt][nt][1] + b1);
                *(half2*)(smemc + (size_t)r1*APITCH_B + col*2) =
                    __floats2half2_rn(acc[mt][nt][2] + b0, acc[mt][nt][3] + b1);
            }
        }
    }

    // ---- stages 1..3: Q/K/V, K=256, chunks 1+s*4+kt ----
    const __half* Ws[3] = { g_WQh, g_WKh, g_WVh };
    float* outs[3] = { g_Q, g_Kf, g_Vf };
    for (int s = 0; s < 3; s++) {
        zero_acc(acc);
        for (int kt = 0; kt < 4; kt++) {
            int c = 1 + s*4 + kt;
            if (c == 12) { CP_WAIT0(); } else { CP_WAIT1(); }
            __syncthreads();
            mma_tile(aAddr + kt*128, bAddr + (uint32_t)(c & 1)*BBYTES, acc);
            __syncthreads();
            int nc = c + 2;
            if (nc <= 12) {
                int ns = (nc - 1) >> 2, nkt = (nc - 1) & 3;
                load_w256(sB, Ws[ns], nkt, nc & 1, tid);
                CP_COMMIT();
            }
        }
        // fused LN -> fp32
        ln_reduce(acc, red, lane, wn, wm2);
        float* outg = outs[s];
        #pragma unroll
        for (int mt = 0; mt < 2; mt++) {
            int gmt = wm2*2 + mt;
            int r0 = gmt*16 + (lane >> 2), r1 = r0 + 8;
            float mu0, rs0, mu1, rs1;
            ln_stats(red, r0, mu0, rs0);
            ln_stats(red, r1, mu1, rs1);
            #pragma unroll
            for (int nt = 0; nt < 4; nt++) {
                int col = wn*32 + nt*8 + (lane & 3)*2;
                float g0 = gdm[col], g1 = gdm[col+1];
                float b0 = bdm[col], b1 = bdm[col+1];
                *(float2*)&outg[(size_t)(p0+r0)*DM + col] = make_float2(
                    (acc[mt][nt][0]-mu0)*rs0*g0 + b0, (acc[mt][nt][1]-mu0)*rs0*g1 + b1);
                *(float2*)&outg[(size_t)(p0+r1)*DM + col] = make_float2(
                    (acc[mt][nt][2]-mu1)*rs1*g0 + b0, (acc[mt][nt][3]-mu1)*rs1*g1 + b1);
            }
        }
        __syncthreads();   // red reuse
    }
}

// ---------------- fused mega-kernel (unchanged from R6 WIN) ----------------
__device__ __forceinline__ void run_stage_mega(const __half* __restrict__ Bw,
                                               const __half* __restrict__ nextBw,
                                               bool final_stage,
                                               float acc[2][4][4],
                                               uint32_t sA, uint32_t sB,
                                               int tid, int lane, int wn, int wm2)
{
    zero_acc(acc);
    const uint32_t aAddr = sA + (uint32_t)(wm2*32 + (lane & 15))*APITCH_B + (lane >> 4)*16;
    const uint32_t bAddr = sB + (uint32_t)(wn*32 + ((lane >> 4) & 1)*8 + (lane & 7))*144
                              + ((lane >> 3) & 1)*16;

    for (int kt = 0; kt < 4; kt++) {
        if (final_stage && kt == 3) { CP_WAIT0(); } else { CP_WAIT1(); }
        __syncthreads();
        mma_tile(aAddr + kt*128, bAddr + (uint32_t)(kt & 1)*BBYTES, acc);
        __syncthreads();

        int ci = kt + 2;
        if (ci < 4)      { load_w256(sB, Bw,     ci,     kt & 1, tid); CP_COMMIT(); }
        else if (nextBw) { load_w256(sB, nextBw, ci - 4, kt & 1, tid); CP_COMMIT(); }
    }
}

__global__ void __launch_bounds__(512) mega_kernel(
    const float* __restrict__ xyz, const float* __restrict__ Wp1)
{
    extern __shared__ char smemc[];
    uint32_t sA = smem_u32(smemc);
    uint32_t sB = sA + ABYTES;

    const int tid  = threadIdx.x;
    const int lane = tid & 31, w = tid >> 5;
    const int wn = w & 7, wm2 = w >> 3;
    const int m0    = blockIdx.x * 64;
    const int pbase = m0 >> 4;
    const int bq    = pbase >> 12;

    __shared__ float rel3[64][3];
    __shared__ int   idxs[64];

    load_w256(sB, g_Wp2h, 0, 0, tid); CP_COMMIT();
    load_w256(sB, g_Wp2h, 1, 1, tid); CP_COMMIT();

    if (tid < 64) {
        int m  = m0 + tid;
        int pt = m >> 4;
        int n  = pt & (NN - 1);
        int id = g_idx[(size_t)pt*KK + (m & 15)];
        idxs[tid] = id;
        const float* xb = xyz + (size_t)bq*NN*3;
        rel3[tid][0] = xb[n*3 + 0] - xb[id*3 + 0];
        rel3[tid][1] = xb[n*3 + 1] - xb[id*3 + 1];
        rel3[tid][2] = xb[n*3 + 2] - xb[id*3 + 2];
    }
    __syncthreads();

    {
        int c0 = (tid & 127)*2;
        int j0 = (tid >> 7)*16;
        float a0 = Wp1[c0*3+0], a1 = Wp1[c0*3+1], a2 = Wp1[c0*3+2];
        float d0 = Wp1[c0*3+3], d1 = Wp1[c0*3+4], d2 = Wp1[c0*3+5];
        #pragma unroll
        for (int j = j0; j < j0 + 16; j++) {
            float h0 = fmaf(a0, rel3[j][0], fmaf(a1, rel3[j][1], a2*rel3[j][2]));
            float h1 = fmaf(d0, rel3[j][0], fmaf(d1, rel3[j][1], d2*rel3[j][2]));
            *(half2*)(smemc + (size_t)j*APITCH_B + c0*2) =
                __floats2half2_rn(fmaxf(h0, 0.f), fmaxf(h1, 0.f));
        }
    }

    float acc[2][4][4];
    float U[2][4][4];

    run_stage_mega(g_Wp2h, g_Wa1h, false, acc, sA, sB, tid, lane, wn, wm2);
    {
        const int r0b  = lane >> 2;
        const int colb = wn*32 + (lane & 3)*2;
        #pragma unroll
        for (int mt = 0; mt < 2; mt++) {
            int gmt = wm2*2 + mt;
            int pt  = pbase + gmt;
            int r0  = gmt*16 + r0b, r1 = r0 + 8;
            const float* qp  = g_Q  + (size_t)pt*DM;
            const float* k0p = g_Kf + ((size_t)(bq << 12) + idxs[r0])*DM;
            const float* k1p = g_Kf + ((size_t)(bq << 12) + idxs[r1])*DM;
            const float* v0p = g_Vf + ((size_t)(bq << 12) + idxs[r0])*DM;
            const float* v1p = g_Vf + ((size_t)(bq << 12) + idxs[r1])*DM;
            #pragma unroll
            for (int nt = 0; nt < 4; nt++) {
                int col = colb + nt*8;
                float2 q  = *(const float2*)(qp  + col);
                float2 ka = *(const float2*)(k0p + col);
                float2 kb = *(const float2*)(k1p + col);
                float2 va = *(const float2*)(v0p + col);
                float2 vb = *(const float2*)(v1p + col);
                float p00 = acc[mt][nt][0], p01 = acc[mt][nt][1];
                float p10 = acc[mt][nt][2], p11 = acc[mt][nt][3];
                *(half2*)(smemc + (size_t)r0*APITCH_B + col*2) =
                    __floats2half2_rn(q.x - ka.x + p00, q.y - ka.y + p01);
                *(half2*)(smemc + (size_t)r1*APITCH_B + col*2) =
                    __floats2half2_rn(q.x - kb.x + p10, q.y - kb.y + p11);
                U[mt][nt][0] = va.x + p00;  U[mt][nt][1] = va.y + p01;
                U[mt][nt][2] = vb.x + p10;  U[mt][nt][3] = vb.y + p11;
            }
        }
    }

    run_stage_mega(g_Wa1h, g_Wa2h, false, acc, sA, sB, tid, lane, wn, wm2);
    {
        const int r0b  = lane >> 2;
        const int colb = wn*32 + (lane & 3)*2;
        #pragma unroll
        for (int mt = 0; mt < 2; mt++) {
            int gmt = wm2*2 + mt;
            int r0  = gmt*16 + r0b, r1 = r0 + 8;
            #pragma unroll
            for (int nt = 0; nt < 4; nt++) {
                int col = colb + nt*8;
                *(half2*)(smemc + (size_t)r0*APITCH_B + col*2) =
                    __floats2half2_rn(fmaxf(acc[mt][nt][0], 0.f), fmaxf(acc[mt][nt][1], 0.f));
                *(half2*)(smemc + (size_t)r1*APITCH_B + col*2) =
                    __floats2half2_rn(fmaxf(acc[mt][nt][2], 0.f), fmaxf(acc[mt][nt][3], 0.f));
            }
        }
    }

    run_stage_mega(g_Wa2h, nullptr, true, acc, sA, sB, tid, lane, wn, wm2);
    {
        const float sc = 0.0625f;
        const int colb = wn*32 + (lane & 3)*2;
        #pragma unroll
        for (int mt = 0; mt < 2; mt++) {
            int pt = pbase + wm2*2 + mt;
            #pragma unroll
            for (int nt = 0; nt < 4; nt++) {
                int col = colb + nt*8;
                float rout[2];
                #pragma unroll
                for (int p = 0; p < 2; p++) {
                    float x0 = acc[mt][nt][p]     * sc;
                    float x1 = acc[mt][nt][2 + p] * sc;
                    float mx = fmaxf(x0, x1);
                    #pragma unroll
                    for (int o = 4; o < 32; o <<= 1)
                        mx = fmaxf(mx, __shfl_xor_sync(0xffffffffu, mx, o));
                    float e0 = __expf(x0 - mx), e1 = __expf(x1 - mx);
                    float s  = e0 + e1;
                    float ww = e0*U[mt][nt][p] + e1*U[mt][nt][2 + p];
                    #pragma unroll
                    for (int o = 4; o < 32; o <<= 1) {
                        s  += __shfl_xor_sync(0xffffffffu, s , o);
                        ww += __shfl_xor_sync(0xffffffffu, ww, o);
                    }
                    rout[p] = ww / s;
                }
                if (lane < 4)
                    *(float2*)&g_res[(size_t)pt*DM + col] = make_float2(rout[0], rout[1]);
            }
        }
    }
}

// ---------------- final via HMMA: proj+LN (GEMM) then post+LN+residual ----------
__global__ void __launch_bounds__(512) finalmma_kernel(
    const float* __restrict__ features, const float* __restrict__ b_post,
    const float* __restrict__ gdm, const float* __restrict__ bdm,
    const float* __restrict__ gdp, const float* __restrict__ bdp,
    float* __restrict__ out)
{
    extern __shared__ char smemc[];
    __shared__ float2 red[64][8];
    uint32_t sA = smem_u32(smemc);
    uint32_t sB = sA + ABYTES;
    const int tid = threadIdx.x, lane = tid & 31, w = tid >> 5;
    const int wn = w & 7, wm2 = w >> 3;
    const int p0 = blockIdx.x * 64;

    load_w256(sB, g_Wprojh, 0, 0, tid); CP_COMMIT();
    load_w256(sB, g_Wprojh, 1, 1, tid); CP_COMMIT();

    // g_res -> A fp16 (64 rows x 256)
    for (int ch = tid; ch < 64*128; ch += 512) {
        int r = ch >> 7, c2 = ch & 127;
        float2 v = *(const float2*)&g_res[(size_t)(p0 + r)*DM + c2*2];
        *(half2*)(smemc + (size_t)r*APITCH_B + c2*4) = __floats2half2_rn(v.x, v.y);
    }

    const uint32_t aAddr = sA + (uint32_t)(wm2*32 + (lane & 15))*APITCH_B + (lane >> 4)*16;
    const uint32_t bAddr = sB + (uint32_t)(wn*32 + ((lane >> 4) & 1)*8 + (lane & 7))*144
                              + ((lane >> 3) & 1)*16;

    float acc[2][4][4];
    zero_acc(acc);
    for (int kt = 0; kt < 4; kt++) {
        if (kt == 3) { CP_WAIT0(); } else { CP_WAIT1(); }
        __syncthreads();
        mma_tile(aAddr + kt*128, bAddr + (uint32_t)(kt & 1)*BBYTES, acc);
        __syncthreads();
        if (kt + 2 < 4) { load_w256(sB, g_Wprojh, kt + 2, kt & 1, tid); CP_COMMIT(); }
    }

    // LN -> z fp16 back into A
    ln_reduce(acc, red, lane, wn, wm2);
    #pragma unroll
    for (int mt = 0; mt < 2; mt++) {
        int gmt = wm2*2 + mt;
        int r0 = gmt*16 + (lane >> 2), r1 = r0 + 8;
        float mu0, rs0, mu1, rs1;
        ln_stats(red, r0, mu0, rs0);
        ln_stats(red, r1, mu1, rs1);
        #pragma unroll
        for (int nt = 0; nt < 4; nt++) {
            int col = wn*32 + nt*8 + (lane & 3)*2;
            float g0 = gdm[col], g1 = gdm[col+1];
            float b0 = bdm[col], b1 = bdm[col+1];
            *(half2*)(smemc + (size_t)r0*APITCH_B + col*2) = __floats2half2_rn(
                (acc[mt][nt][0]-mu0)*rs0*g0 + b0, (acc[mt][nt][1]-mu0)*rs0*g1 + b1);
            *(half2*)(smemc + (size_t)r1*APITCH_B + col*2) = __floats2half2_rn(
                (acc[mt][nt][2]-mu1)*rs1*g0 + b0, (acc[mt][nt][3]-mu1)*rs1*g1 + b1);
        }
    }
    __syncthreads();

    // post: o[r][po] = b_post[po] + sum_j z[r][j] * WpostT[j][po]  (SIMT from smem)
    const int po = tid & 63, rg = tid >> 6;      // rg 0..7
    float o[8];
    #pragma unroll
    for (int i = 0; i < 8; i++) o[i] = b_post[po];
    for (int j2 = 0; j2 < 128; j2++) {
        float w0 = g_WpostT[(2*j2)*DP + po];
        float w1 = g_WpostT[(2*j2+1)*DP + po];
        #pragma unroll
        for (int i = 0; i < 8; i++) {
            int r = rg*8 + i;
            half2 zz = *(const half2*)(smemc + (size_t)r*APITCH_B + j2*4);
            float2 zf = __half22float2(zz);
            o[i] = fmaf(w0, zf.x, fmaf(w1, zf.y, o[i]));
        }
    }

    float* obuf = (float*)(smemc + ABYTES);      // reuse B region, pitch 68
    #pragma unroll
    for (int i = 0; i < 8; i++) obuf[(rg*8 + i)*68 + po] = o[i];
    __syncthreads();

    // LN(64) + residual: warp w2 handles rows w2*4..w2*4+3
    #pragma unroll
    for (int i = 0; i < 4; i++) {
        int row = w*4 + i;
        float x0 = obuf[row*68 + lane], x1 = obuf[row*68 + 32 + lane];
        float s = x0 + x1, s2 = x0*x0 + x1*x1;
        warp_bfly2(s, s2);
        float mu = s*(1.f/DP), var = s2*(1.f/DP) - mu*mu;
        float rs = rsqrtf(var + 1e-5f);
        size_t base = (size_t)(p0 + row)*DP;
        out[base + lane]      = (x0-mu)*rs*gdp[lane]      + bdp[lane]      + features[base + lane];
        out[base + 32 + lane] = (x1-mu)*rs*gdp[32 + lane] + bdp[32 + lane] + features[base + 32 + lane];
    }
}

// ---------------- launch ----------------
extern "C" void kernel_launch(void* const* d_in, const int* in_sizes, int n_in,
                              void* d_out, int out_size)
{
    const float* xyz      = (const float*)d_in[0];
    const float* features = (const float*)d_in[1];
    const float* W_pre    = (const float*)d_in[2];
    const float* b_pre    = (const float*)d_in[3];
    const float* W_post   = (const float*)d_in[4];
    const float* b_post   = (const float*)d_in[5];
    const float* Wp1      = (const float*)d_in[6];
    const float* Wp2      = (const float*)d_in[7];
    const float* Wa1      = (const float*)d_in[8];
    const float* Wa2      = (const float*)d_in[9];
    const float* WQ       = (const float*)d_in[10];
    const float* WK       = (const float*)d_in[11];
    const float* WV       = (const float*)d_in[12];
    const float* Wproj    = (const float*)d_in[13];
    const float* g_dm     = (const float*)d_in[14];
    const float* b_dm     = (const float*)d_in[15];
    const float* g_dp     = (const float*)d_in[16];
    const float* b_dp     = (const float*)d_in[17];
    float* out = (float*)d_out;

    cudaFuncSetAttribute(knn_kernel, cudaFuncAttributeMaxDynamicSharedMemorySize,
                         NN * (int)sizeof(float4));
    cudaFuncSetAttribute(mega_kernel,     cudaFuncAttributeMaxDynamicSharedMemorySize, MEGA_SMEM);
    cudaFuncSetAttribute(qkvmma_kernel,   cudaFuncAttributeMaxDynamicSharedMemorySize, MEGA_SMEM);
    cudaFuncSetAttribute(finalmma_kernel, cudaFuncAttributeMaxDynamicSharedMemorySize, MEGA_SMEM);

    prep_kernel<<<256, 256>>>(W_pre, WQ, WK, WV, Wproj, W_post, Wp2, Wa1, Wa2);
    knn_kernel<<<BB*(NN/256), 256, NN*sizeof(float4)>>>(xyz);
    qkvmma_kernel<<<NPTS/64, 512, MEGA_SMEM>>>(features, b_pre, g_dm, b_dm);

    mega_kernel<<<MTOT/64, 512, MEGA_SMEM>>>(xyz, Wp1);

    finalmma_kernel<<<NPTS/64, 512, MEGA_SMEM>>>(features, b_post, g_dm, b_dm,
                                                 g_dp, b_dp, out);
}